// round 11
// baseline (speedup 1.0000x reference)
#include <cuda_runtime.h>
#include <cstdint>

#define N_NODES 100000
#define N_EDGES 1600000
#define NCHUNK 196       // 196*512 >= N_NODES (scan chunks of 512)
#define NBG 592          // 4 blocks/SM x 148 SMs -> co-resident, barrier-safe
#define NTG 256
#define NW1 100000       // layer-1 mask words (32 elems each)
#define NW2 200000       // layer-2 mask words
#define NWTOT (NW1 + NW2)

// ---------------- scratch (device globals; no allocation allowed) ----------
__device__ float g_y[N_NODES * 32];     // x @ W1_l
__device__ float g_z[N_NODES * 32];     // x @ W1_r
__device__ float g_h1[N_NODES * 32];
__device__ int2  g_edge[N_EDGES];       // packed (src, dst)
__device__ int   g_csr[N_EDGES];        // src ids grouped by dst
__device__ int   g_off[N_NODES + 1];    // counts -> exclusive offsets
__device__ int   g_part[N_NODES + 512]; // scan partials
__device__ int   g_cur[N_NODES];        // bucket cursors
__device__ int   g_bsum[256];
__device__ uint32_t g_mask1[NW1];       // dropout masks layer 1 (bit=1: dropped)
__device__ uint32_t g_mask2[NW2];       // dropout masks layer 2
__device__ int   g_is64;
__device__ unsigned g_arrive;
__device__ unsigned g_release;

// ---------------- JAX threefry2x32 (partitionable scheme) ------------------
struct TF2 { uint32_t a, b; };

__host__ __device__ constexpr uint32_t rotl32(uint32_t v, int r) {
    return (v << r) | (v >> (32 - r));
}

__host__ __device__ constexpr TF2 threefry(uint32_t k0, uint32_t k1,
                                           uint32_t x0, uint32_t x1) {
    const uint32_t ks0 = k0, ks1 = k1, ks2 = k0 ^ k1 ^ 0x1BD11BDAu;
    const int ra[4] = {13, 15, 26, 6};
    const int rb[4] = {17, 29, 16, 24};
    x0 += ks0; x1 += ks1;
#pragma unroll
    for (int i = 0; i < 4; i++) { x0 += x1; x1 = rotl32(x1, ra[i]); x1 ^= x0; }
    x0 += ks1; x1 += ks2 + 1u;
#pragma unroll
    for (int i = 0; i < 4; i++) { x0 += x1; x1 = rotl32(x1, rb[i]); x1 ^= x0; }
    x0 += ks2; x1 += ks0 + 2u;
#pragma unroll
    for (int i = 0; i < 4; i++) { x0 += x1; x1 = rotl32(x1, ra[i]); x1 ^= x0; }
    x0 += ks0; x1 += ks1 + 3u;
#pragma unroll
    for (int i = 0; i < 4; i++) { x0 += x1; x1 = rotl32(x1, rb[i]); x1 ^= x0; }
    x0 += ks1; x1 += ks2 + 4u;
#pragma unroll
    for (int i = 0; i < 4; i++) { x0 += x1; x1 = rotl32(x1, ra[i]); x1 ^= x0; }
    x0 += ks2; x1 += ks0 + 5u;
    return {x0, x1};
}

constexpr TF2 DK0 = threefry(0u, 42u, 0u, 0u);
constexpr TF2 DK1 = threefry(0u, 42u, 0u, 1u);

template <uint32_t K0, uint32_t K1>
__device__ __forceinline__ bool drop_bit(uint32_t j) {
    TF2 r = threefry(K0, K1, 0u, j);
    return ((r.a ^ r.b) >> 31) != 0;   // MSB set -> u >= 0.5 -> dropped
}

// ---------------- packed f32x2 helpers (sm_103a) ---------------------------
typedef unsigned long long ULL;
__device__ __forceinline__ ULL pk2(float x, float y) {
    ULL r;
    asm("mov.b64 %0, {%1, %2};" : "=l"(r) : "f"(x), "f"(y));
    return r;
}
__device__ __forceinline__ ULL fma2(ULL a, ULL b, ULL c) {
    ULL d;
    asm("fma.rn.f32x2 %0, %1, %2, %3;" : "=l"(d) : "l"(a), "l"(b), "l"(c));
    return d;
}
__device__ __forceinline__ void upk2(ULL v, float& x, float& y) {
    asm("mov.b64 {%0, %1}, %2;" : "=f"(x), "=f"(y) : "l"(v));
}

// ---------------- k_pre: dense pre-GEMM + all per-replay resets -------------
__global__ void __launch_bounds__(256) k_pre(const float* __restrict__ x,
                      const float* __restrict__ Wl,
                      const float* __restrict__ Wr,
                      const uint32_t* __restrict__ ei) {
    __shared__ float2 swlr[64 * 32];      // (Wl, Wr) pairs, 16KB
    __shared__ float  rows[8][4][64];     // 8KB
    int tid = threadIdx.x;
    for (int i = tid; i < 2048; i += 256) swlr[i] = make_float2(Wl[i], Wr[i]);
    int gt = blockIdx.x * 256 + tid;
    if (gt <= N_NODES) g_off[gt] = 0;
    if (blockIdx.x == 0 && tid == 0) {
        g_arrive = 0u;
        g_release = 0u;
        int is64 = 1;
        for (int k = 0; k < 64; k++)
            if (ei[2 * k + 1] != 0u) { is64 = 0; break; }
        g_is64 = is64;
    }
    int w = tid >> 5, lane = tid & 31;
    int nb = blockIdx.x * 32 + w * 4;     // grid = 3125 exact
#pragma unroll
    for (int n = 0; n < 4; n++) {
        rows[w][n][lane]      = x[(nb + n) * 64 + lane];
        rows[w][n][32 + lane] = x[(nb + n) * 64 + 32 + lane];
    }
    __syncthreads();
    ULL acc[4];
#pragma unroll
    for (int n = 0; n < 4; n++) acc[n] = pk2(0.f, 0.f);
#pragma unroll
    for (int k = 0; k < 64; k++) {
        float2 wv = swlr[k * 32 + lane];
        ULL wp = pk2(wv.x, wv.y);
#pragma unroll
        for (int n = 0; n < 4; n++) {
            float xv = rows[w][n][k];
            acc[n] = fma2(pk2(xv, xv), wp, acc[n]);
        }
    }
#pragma unroll
    for (int n = 0; n < 4; n++) {
        float yl, yr;
        upk2(acc[n], yl, yr);
        g_y[(nb + n) * 32 + lane] = yl;
        g_z[(nb + n) * 32 + lane] = yr;
    }
}

// ---------------- k_graph: CSR build + dropout-mask precompute ---------------
// 592 blocks x 256 (4 CTAs/SM, ~1KB smem) -> co-resident, barrier-safe.
__global__ void __launch_bounds__(NTG, 4) k_graph(const uint32_t* __restrict__ ei) {
    __shared__ int sh[NTG];
    const int tid = threadIdx.x;
    const int bid = blockIdx.x;
    const int lane = tid & 31;
    unsigned target = 0;

    auto GBAR = [&]() {
        __syncthreads();
        __threadfence();
        target += 1;
        if (tid == 0) {
            unsigned a = atomicAdd(&g_arrive, 1u) + 1u;
            if (a == target * NBG) {
                *((volatile unsigned*)&g_release) = target;
            } else {
                while (*((volatile unsigned*)&g_release) < target) __nanosleep(64);
            }
        }
        __syncthreads();
    };

    // ---- phase 1: edges (pack + histogram) interleaved with mask generation.
    // Edge loads/atomics are long-latency; threefry is pure ALU -> the
    // interleave hides memory latency behind hash work within each warp.
    {
        int is64 = g_is64;
        const int ET = NBG * NTG;                 // edge stride (threads)
        const int WT = NBG * (NTG / 32);          // mask stride (warps)
        int ew = bid * NTG + (tid & ~31);         // warp-uniform edge base
        int mw = bid * (NTG / 32) + (tid >> 5);   // warp mask-word cursor
        while (ew < N_EDGES || mw < NWTOT) {
            if (ew < N_EDGES) {
                int e = ew + lane;
                if (e < N_EDGES) {
                    int s, d;
                    if (is64) {
                        uint2 sv = reinterpret_cast<const uint2*>(ei)[e];
                        uint2 dv = reinterpret_cast<const uint2*>(ei)[N_EDGES + e];
                        s = (int)sv.x; d = (int)dv.x;
                    } else {
                        s = (int)ei[e];
                        d = (int)ei[N_EDGES + e];
                    }
                    g_edge[e] = make_int2(s, d);
                    atomicAdd(&g_off[d], 1);
                }
                ew += ET;
            }
            if (mw < NWTOT) {
                uint32_t word;
                if (mw < NW1) {
                    word = __ballot_sync(0xffffffffu,
                           drop_bit<DK0.a, DK0.b>((uint32_t)mw * 32u + lane));
                    if (lane == 0) g_mask1[mw] = word;
                } else {
                    int m2 = mw - NW1;
                    word = __ballot_sync(0xffffffffu,
                           drop_bit<DK1.a, DK1.b>((uint32_t)m2 * 32u + lane));
                    if (lane == 0) g_mask2[m2] = word;
                }
                mw += WT;
            }
        }
    }
    GBAR();   // 1

    // ---- phase 2: per-chunk exclusive scan (512 counts/chunk, 2/thread) ----
    if (bid < NCHUNK) {
        int i0 = bid * 512 + tid * 2;
        int v0 = (i0     < N_NODES) ? __ldcg(&g_off[i0])     : 0;
        int v1 = (i0 + 1 < N_NODES) ? __ldcg(&g_off[i0 + 1]) : 0;
        int s2 = v0 + v1;
        sh[tid] = s2;
        __syncthreads();
        for (int o = 1; o < NTG; o <<= 1) {
            int t = (tid >= o) ? sh[tid - o] : 0;
            __syncthreads();
            sh[tid] += t;
            __syncthreads();
        }
        int ex = sh[tid] - s2;
        if (i0     < N_NODES) g_part[i0]     = ex;
        if (i0 + 1 < N_NODES) g_part[i0 + 1] = ex + v0;
        if (tid == NTG - 1) g_bsum[bid] = sh[NTG - 1];
    }
    GBAR();   // 2

    // ---- phase 3: apply (reduce preceding chunk totals, write offs+cursors) --
    if (bid < NCHUNK) {
        int v = (tid < bid) ? __ldcg(&g_bsum[tid]) : 0;   // bid <= 195 < 256
        sh[tid] = v;
        __syncthreads();
        for (int o = NTG / 2; o > 0; o >>= 1) {
            if (tid < o) sh[tid] += sh[tid + o];
            __syncthreads();
        }
        int base = sh[0];
        for (int idx = tid; idx < 512; idx += NTG) {
            int i = bid * 512 + idx;
            if (i < N_NODES) {
                int o = g_part[i] + base;
                g_off[i] = o;
                g_cur[i] = o;
            }
        }
        if (bid == 0 && tid == 0) g_off[N_NODES] = N_EDGES;
    }
    GBAR();   // 3

    // ---- phase 4: bucket scatter (CSR fill) ----
    for (int e = bid * NTG + tid; e < N_EDGES; e += NBG * NTG) {
        int2 p = g_edge[e];
        int pos = atomicAdd(&g_cur[p.y], 1);
        g_csr[pos] = p.x;
    }
}

// float4 gather-sum of a node's neighbor rows (warp-collective).
// lane = r*8+c: r selects 1 of 4 rows per step, c the float4 column.
__device__ __forceinline__ float4 gather4(const float* __restrict__ buf,
                                          int beg, int end, int r, int c) {
    float4 acc = make_float4(0.f, 0.f, 0.f, 0.f);
    for (int j = beg; j < end; j += 4) {
        int jr = j + r;
        if (jr < end) {
            int s = __ldg(g_csr + jr);
            float4 v = __ldg(reinterpret_cast<const float4*>(buf + s * 32) + c);
            acc.x += v.x; acc.y += v.y; acc.z += v.z; acc.w += v.w;
        }
    }
    // combine the 4 r-groups (xor 8, 16)
#pragma unroll
    for (int o = 8; o <= 16; o <<= 1) {
        acc.x += __shfl_xor_sync(0xffffffffu, acc.x, o);
        acc.y += __shfl_xor_sync(0xffffffffu, acc.y, o);
        acc.z += __shfl_xor_sync(0xffffffffu, acc.z, o);
        acc.w += __shfl_xor_sync(0xffffffffu, acc.w, o);
    }
    return acc;
}

// layer 1: warp per node; float4 gather, bias+z+lrelu, mask-based dropout
__global__ void k_agg1(const float* __restrict__ b) {
    int w = threadIdx.x >> 5, lane = threadIdx.x & 31;
    int r = lane >> 3, c = lane & 7;
    int node = blockIdx.x * 8 + w;                    // grid = 12500 exact
    int beg = g_off[node], end = g_off[node + 1];
    float4 acc = gather4(g_y, beg, end, r, c);
    if (r == 0) {
        float inv = 1.0f / fmaxf((float)(end - beg), 1.0f);
        float4 z  = __ldg(reinterpret_cast<const float4*>(g_z + node * 32) + c);
        float4 bb = __ldg(reinterpret_cast<const float4*>(b) + c);
        uint32_t m = __ldg(&g_mask1[node]);
        float4 o;
        float v;
        v = fmaf(acc.x, inv, bb.x + z.x); v = v > 0.f ? v : 0.01f * v;
        o.x = ((m >> (4 * c + 0)) & 1u) ? 0.f : 2.0f * v;
        v = fmaf(acc.y, inv, bb.y + z.y); v = v > 0.f ? v : 0.01f * v;
        o.y = ((m >> (4 * c + 1)) & 1u) ? 0.f : 2.0f * v;
        v = fmaf(acc.z, inv, bb.z + z.z); v = v > 0.f ? v : 0.01f * v;
        o.z = ((m >> (4 * c + 2)) & 1u) ? 0.f : 2.0f * v;
        v = fmaf(acc.w, inv, bb.w + z.w); v = v > 0.f ? v : 0.01f * v;
        o.w = ((m >> (4 * c + 3)) & 1u) ? 0.f : 2.0f * v;
        reinterpret_cast<float4*>(g_h1 + node * 32)[c] = o;
    }
}

// layer 2 fused: float4 gather-mean, across-node packed GEMM, mask dropout,
// l2norm. 4 nodes/warp.
__global__ void __launch_bounds__(256) k_agg2(const float* __restrict__ Wl,
                       const float* __restrict__ b,
                       const float* __restrict__ Wr,
                       float* __restrict__ out) {
    __shared__ ULL swlx[32 * 32], swly[32 * 32];    // dup(Wl[k][lane]), dup(Wl[k][32+lane])
    __shared__ ULL swrx[32 * 32], swry[32 * 32];    // 32KB total
    __shared__ float rowsM[8][32][4];               // [warp][k][node] 4KB
    __shared__ float rowsH[8][32][4];               // 4KB
    int tid = threadIdx.x;
    for (int i = tid; i < 1024; i += 256) {
        int k = i >> 5, l = i & 31;
        float wl0 = Wl[k * 64 + l], wl1 = Wl[k * 64 + 32 + l];
        float wr0 = Wr[k * 64 + l], wr1 = Wr[k * 64 + 32 + l];
        swlx[i] = pk2(wl0, wl0); swly[i] = pk2(wl1, wl1);
        swrx[i] = pk2(wr0, wr0); swry[i] = pk2(wr1, wr1);
    }
    __syncthreads();
    int w = tid >> 5, lane = tid & 31;
    int r = lane >> 3, c = lane & 7;
    int nb = blockIdx.x * 32 + w * 4;                 // grid = 3125 exact
#pragma unroll
    for (int n = 0; n < 4; n++) {
        int node = nb + n;
        int beg = g_off[node], end = g_off[node + 1];
        float4 acc = gather4(g_h1, beg, end, r, c);
        if (r == 0) {
            float inv = 1.0f / fmaxf((float)(end - beg), 1.0f);
            float4 h = __ldg(reinterpret_cast<const float4*>(g_h1 + node * 32) + c);
            rowsM[w][4 * c + 0][n] = acc.x * inv;
            rowsM[w][4 * c + 1][n] = acc.y * inv;
            rowsM[w][4 * c + 2][n] = acc.z * inv;
            rowsM[w][4 * c + 3][n] = acc.w * inv;
            rowsH[w][4 * c + 0][n] = h.x;
            rowsH[w][4 * c + 1][n] = h.y;
            rowsH[w][4 * c + 2][n] = h.z;
            rowsH[w][4 * c + 3][n] = h.w;
        }
    }
    __syncwarp();
    float bb0 = b[lane], bb1 = b[32 + lane];
    ULL accA01 = pk2(bb0, bb0), accA23 = pk2(bb0, bb0);
    ULL accB01 = pk2(bb1, bb1), accB23 = pk2(bb1, bb1);
#pragma unroll
    for (int k = 0; k < 32; k++) {
        float4 m4 = *reinterpret_cast<const float4*>(&rowsM[w][k][0]);
        float4 h4 = *reinterpret_cast<const float4*>(&rowsH[w][k][0]);
        ULL m01 = pk2(m4.x, m4.y), m23 = pk2(m4.z, m4.w);
        ULL h01 = pk2(h4.x, h4.y), h23 = pk2(h4.z, h4.w);
        ULL wlx = swlx[k * 32 + lane], wly = swly[k * 32 + lane];
        ULL wrx = swrx[k * 32 + lane], wry = swry[k * 32 + lane];
        accA01 = fma2(m01, wlx, accA01); accA01 = fma2(h01, wrx, accA01);
        accA23 = fma2(m23, wlx, accA23); accA23 = fma2(h23, wrx, accA23);
        accB01 = fma2(m01, wly, accB01); accB01 = fma2(h01, wry, accB01);
        accB23 = fma2(m23, wly, accB23); accB23 = fma2(h23, wry, accB23);
    }
    float a0[4], a1[4];
    upk2(accA01, a0[0], a0[1]); upk2(accA23, a0[2], a0[3]);
    upk2(accB01, a1[0], a1[1]); upk2(accB23, a1[2], a1[3]);
#pragma unroll
    for (int n = 0; n < 4; n++) {
        int node = nb + n;
        uint32_t m0 = __ldg(&g_mask2[node * 2]);
        uint32_t m1 = __ldg(&g_mask2[node * 2 + 1]);
        float v0 = ((m0 >> lane) & 1u) ? 0.f : 2.0f * a0[n];
        float v1 = ((m1 >> lane) & 1u) ? 0.f : 2.0f * a1[n];
        float ss = v0 * v0 + v1 * v1;
#pragma unroll
        for (int o = 16; o > 0; o >>= 1)
            ss += __shfl_xor_sync(0xffffffffu, ss, o);
        float scale = 1.0f / fmaxf(sqrtf(ss), 1e-12f);
        out[node * 64 + lane]      = v0 * scale;
        out[node * 64 + 32 + lane] = v1 * scale;
    }
}

// ---------------- launch -----------------------------------------------------
extern "C" void kernel_launch(void* const* d_in, const int* in_sizes, int n_in,
                              void* d_out, int out_size) {
    const float*    x   = (const float*)d_in[0];
    const uint32_t* ei  = (const uint32_t*)d_in[1];   // int32 or int64 (detected)
    const float*    W1l = (const float*)d_in[2];
    const float*    b1  = (const float*)d_in[3];
    const float*    W1r = (const float*)d_in[4];
    const float*    W2l = (const float*)d_in[5];
    const float*    b2  = (const float*)d_in[6];
    const float*    W2r = (const float*)d_in[7];
    float* out = (float*)d_out;

    k_pre<<<N_NODES / 32, 256>>>(x, W1l, W1r, ei);     // 3125 blocks
    k_graph<<<NBG, NTG>>>(ei);                         // CSR + dropout masks
    k_agg1<<<N_NODES / 8, 256>>>(b1);                  // 12500 blocks
    k_agg2<<<N_NODES / 32, 256>>>(W2l, b2, W2r, out);  // 3125 blocks
}

// round 13
// speedup vs baseline: 1.0995x; 1.0995x over previous
#include <cuda_runtime.h>
#include <cstdint>

#define N_NODES 100000
#define N_EDGES 1600000
#define SCAN_BLK 512
#define NSCAN_BLKS 196   // 196*512 >= N_NODES

// ---------------- scratch (device globals; no allocation allowed) ----------
__device__ float g_y[N_NODES * 32];     // x @ W1_l
__device__ float g_z[N_NODES * 32];     // x @ W1_r
__device__ float g_h1[N_NODES * 32];
__device__ float g_m2[N_NODES * 32];    // layer-2 gathered mean
__device__ int2  g_edge[N_EDGES];       // packed (src, dst)
__device__ int   g_csr[N_EDGES];        // src ids grouped by dst
__device__ int   g_off[N_NODES + 1];    // counts -> exclusive offsets
__device__ int   g_part[N_NODES];       // scan partials
__device__ int   g_cur[N_NODES];        // bucket cursors
__device__ int   g_bsum[256];
__device__ int   g_is64;

// ---------------- JAX threefry2x32 (partitionable scheme) ------------------
struct TF2 { uint32_t a, b; };

__host__ __device__ constexpr uint32_t rotl32(uint32_t v, int r) {
    return (v << r) | (v >> (32 - r));
}

__host__ __device__ constexpr TF2 threefry(uint32_t k0, uint32_t k1,
                                           uint32_t x0, uint32_t x1) {
    const uint32_t ks0 = k0, ks1 = k1, ks2 = k0 ^ k1 ^ 0x1BD11BDAu;
    const int ra[4] = {13, 15, 26, 6};
    const int rb[4] = {17, 29, 16, 24};
    x0 += ks0; x1 += ks1;
#pragma unroll
    for (int i = 0; i < 4; i++) { x0 += x1; x1 = rotl32(x1, ra[i]); x1 ^= x0; }
    x0 += ks1; x1 += ks2 + 1u;
#pragma unroll
    for (int i = 0; i < 4; i++) { x0 += x1; x1 = rotl32(x1, rb[i]); x1 ^= x0; }
    x0 += ks2; x1 += ks0 + 2u;
#pragma unroll
    for (int i = 0; i < 4; i++) { x0 += x1; x1 = rotl32(x1, ra[i]); x1 ^= x0; }
    x0 += ks0; x1 += ks1 + 3u;
#pragma unroll
    for (int i = 0; i < 4; i++) { x0 += x1; x1 = rotl32(x1, rb[i]); x1 ^= x0; }
    x0 += ks1; x1 += ks2 + 4u;
#pragma unroll
    for (int i = 0; i < 4; i++) { x0 += x1; x1 = rotl32(x1, ra[i]); x1 ^= x0; }
    x0 += ks2; x1 += ks0 + 5u;
    return {x0, x1};
}

constexpr TF2 DK0 = threefry(0u, 42u, 0u, 0u);
constexpr TF2 DK1 = threefry(0u, 42u, 0u, 1u);

template <uint32_t K0, uint32_t K1>
__device__ __forceinline__ bool drop_bit(uint32_t j) {
    TF2 r = threefry(K0, K1, 0u, j);
    return ((r.a ^ r.b) >> 31) != 0;   // MSB set -> u >= 0.5 -> dropped
}

// ---------------- packed f32x2 helpers (sm_103a) ---------------------------
typedef unsigned long long ULL;
__device__ __forceinline__ ULL pk2(float x, float y) {
    ULL r;
    asm("mov.b64 %0, {%1, %2};" : "=l"(r) : "f"(x), "f"(y));
    return r;
}
__device__ __forceinline__ ULL fma2(ULL a, ULL b, ULL c) {
    ULL d;
    asm("fma.rn.f32x2 %0, %1, %2, %3;" : "=l"(d) : "l"(a), "l"(b), "l"(c));
    return d;
}
__device__ __forceinline__ void upk2(ULL v, float& x, float& y) {
    asm("mov.b64 {%0, %1}, %2;" : "=f"(x), "=f"(y) : "l"(v));
}

// ---------------- k_pre: dense pre-GEMM + resets + dtype detect -------------
__global__ void __launch_bounds__(256) k_pre(const float* __restrict__ x,
                      const float* __restrict__ Wl,
                      const float* __restrict__ Wr,
                      const uint32_t* __restrict__ ei) {
    __shared__ float2 swlr[64 * 32];      // (Wl, Wr) pairs, 16KB
    __shared__ float  rows[8][4][64];     // 8KB
    int tid = threadIdx.x;
    for (int i = tid; i < 2048; i += 256) swlr[i] = make_float2(Wl[i], Wr[i]);
    int gt = blockIdx.x * 256 + tid;
    if (gt <= N_NODES) g_off[gt] = 0;
    if (blockIdx.x == 0 && tid == 0) {
        int is64 = 1;
        for (int k = 0; k < 64; k++)
            if (ei[2 * k + 1] != 0u) { is64 = 0; break; }
        g_is64 = is64;
    }
    int w = tid >> 5, lane = tid & 31;
    int nb = blockIdx.x * 32 + w * 4;     // grid = 3125 exact
#pragma unroll
    for (int n = 0; n < 4; n++) {
        rows[w][n][lane]      = x[(nb + n) * 64 + lane];
        rows[w][n][32 + lane] = x[(nb + n) * 64 + 32 + lane];
    }
    __syncthreads();
    ULL acc[4];
#pragma unroll
    for (int n = 0; n < 4; n++) acc[n] = pk2(0.f, 0.f);
#pragma unroll
    for (int k = 0; k < 64; k++) {
        float2 wv = swlr[k * 32 + lane];
        ULL wp = pk2(wv.x, wv.y);
#pragma unroll
        for (int n = 0; n < 4; n++) {
            float xv = rows[w][n][k];
            acc[n] = fma2(pk2(xv, xv), wp, acc[n]);
        }
    }
#pragma unroll
    for (int n = 0; n < 4; n++) {
        float yl, yr;
        upk2(acc[n], yl, yr);
        g_y[(nb + n) * 32 + lane] = yl;
        g_z[(nb + n) * 32 + lane] = yr;
    }
}

// ---------------- CSR build ---------------------------------------------------
__global__ void k_prep(const uint32_t* __restrict__ ei) {
    int e = blockIdx.x * blockDim.x + threadIdx.x;
    if (e >= N_EDGES) return;
    int s, d;
    if (g_is64) {
        uint2 sv = reinterpret_cast<const uint2*>(ei)[e];
        uint2 dv = reinterpret_cast<const uint2*>(ei)[N_EDGES + e];
        s = (int)sv.x; d = (int)dv.x;
    } else {
        s = (int)ei[e];
        d = (int)ei[N_EDGES + e];
    }
    g_edge[e] = make_int2(s, d);
    atomicAdd(&g_off[d], 1);
}

__global__ void k_scan_a() {
    __shared__ int sh[SCAN_BLK];
    int i = blockIdx.x * SCAN_BLK + threadIdx.x;
    int v = (i < N_NODES) ? g_off[i] : 0;
    sh[threadIdx.x] = v;
    __syncthreads();
    for (int o = 1; o < SCAN_BLK; o <<= 1) {
        int t = (threadIdx.x >= o) ? sh[threadIdx.x - o] : 0;
        __syncthreads();
        sh[threadIdx.x] += t;
        __syncthreads();
    }
    if (i < N_NODES) g_part[i] = sh[threadIdx.x] - v;    // exclusive in-block
    if (threadIdx.x == SCAN_BLK - 1) g_bsum[blockIdx.x] = sh[threadIdx.x];
}

__global__ void k_scan_b() {                             // 1 block of 256
    __shared__ int sh[256];
    int v = (threadIdx.x < NSCAN_BLKS) ? g_bsum[threadIdx.x] : 0;
    sh[threadIdx.x] = v;
    __syncthreads();
    for (int o = 1; o < 256; o <<= 1) {
        int t = (threadIdx.x >= o) ? sh[threadIdx.x - o] : 0;
        __syncthreads();
        sh[threadIdx.x] += t;
        __syncthreads();
    }
    if (threadIdx.x < NSCAN_BLKS) g_bsum[threadIdx.x] = sh[threadIdx.x] - v;
}

__global__ void k_scan_c() {
    int i = blockIdx.x * SCAN_BLK + threadIdx.x;
    if (i < N_NODES) {
        int o = g_part[i] + g_bsum[i / SCAN_BLK];
        g_off[i] = o;
        g_cur[i] = o;
    }
    if (i == 0) g_off[N_NODES] = N_EDGES;
}

__global__ void k_bucket() {
    int e = blockIdx.x * blockDim.x + threadIdx.x;
    if (e >= N_EDGES) return;
    int2 p = g_edge[e];
    int pos = atomicAdd(&g_cur[p.y], 1);
    g_csr[pos] = p.x;
}

// ---------------- gathers (ILP-8) --------------------------------------------
__device__ __forceinline__ float gather_sum8(const float* __restrict__ buf,
                                             int beg, int end, int lane) {
    float acc = 0.f;
    int j = beg;
    for (; j + 8 <= end; j += 8) {
        int s0 = __ldg(g_csr + j),     s1 = __ldg(g_csr + j + 1);
        int s2 = __ldg(g_csr + j + 2), s3 = __ldg(g_csr + j + 3);
        int s4 = __ldg(g_csr + j + 4), s5 = __ldg(g_csr + j + 5);
        int s6 = __ldg(g_csr + j + 6), s7 = __ldg(g_csr + j + 7);
        float v0 = __ldg(buf + s0 * 32 + lane);
        float v1 = __ldg(buf + s1 * 32 + lane);
        float v2 = __ldg(buf + s2 * 32 + lane);
        float v3 = __ldg(buf + s3 * 32 + lane);
        float v4 = __ldg(buf + s4 * 32 + lane);
        float v5 = __ldg(buf + s5 * 32 + lane);
        float v6 = __ldg(buf + s6 * 32 + lane);
        float v7 = __ldg(buf + s7 * 32 + lane);
        acc += ((v0 + v1) + (v2 + v3)) + ((v4 + v5) + (v6 + v7));
    }
    for (; j < end; j++)
        acc += __ldg(buf + __ldg(g_csr + j) * 32 + lane);
    return acc;
}

// layer 1: warp per node; gather-sum y rows, fuse bias+z+lrelu+dropout
__global__ void k_agg1(const float* __restrict__ b) {
    int w = threadIdx.x >> 5, lane = threadIdx.x & 31;
    int node = blockIdx.x * 8 + w;                    // grid = 12500 exact
    int beg = g_off[node], end = g_off[node + 1];
    float acc = gather_sum8(g_y, beg, end, lane);
    float inv = 1.0f / fmaxf((float)(end - beg), 1.0f);
    float v = fmaf(acc, inv, b[lane] + g_z[node * 32 + lane]);
    v = v > 0.f ? v : 0.01f * v;
    uint32_t jj = (uint32_t)(node * 32 + lane);
    g_h1[jj] = drop_bit<DK0.a, DK0.b>(jj) ? 0.f : 2.0f * v;
}

// layer 2 gather: warp per node; mean of h1 neighbor rows -> g_m2
__global__ void k_gather2() {
    int w = threadIdx.x >> 5, lane = threadIdx.x & 31;
    int node = blockIdx.x * 8 + w;                    // grid = 12500 exact
    int beg = g_off[node], end = g_off[node + 1];
    float acc = gather_sum8(g_h1, beg, end, lane);
    float inv = 1.0f / fmaxf((float)(end - beg), 1.0f);
    g_m2[node * 32 + lane] = acc * inv;
}

// layer 2 dense: GEMMs (4 nodes/warp, packed weights) + dropout + l2norm
__global__ void __launch_bounds__(256) k_gemm2(const float* __restrict__ Wl,
                       const float* __restrict__ b,
                       const float* __restrict__ Wr,
                       float* __restrict__ out) {
    __shared__ float2 swl2[32 * 32], swr2[32 * 32];   // 8KB + 8KB
    __shared__ float  rows[8][4][64];                 // 8KB
    int tid = threadIdx.x;
    for (int i = tid; i < 1024; i += 256) {
        int k = i >> 5, c = i & 31;
        swl2[i] = make_float2(Wl[k * 64 + c], Wl[k * 64 + 32 + c]);
        swr2[i] = make_float2(Wr[k * 64 + c], Wr[k * 64 + 32 + c]);
    }
    __syncthreads();
    int w = tid >> 5, lane = tid & 31;
    int nb = blockIdx.x * 32 + w * 4;                 // grid = 3125 exact
#pragma unroll
    for (int n = 0; n < 4; n++) {
        int node = nb + n;
        rows[w][n][lane]      = g_m2[node * 32 + lane];
        rows[w][n][32 + lane] = g_h1[node * 32 + lane];
    }
    __syncwarp();
    float bb0 = b[lane], bb1 = b[32 + lane];
    float a0[4], a1[4];
#pragma unroll
    for (int n = 0; n < 4; n++) { a0[n] = bb0; a1[n] = bb1; }
#pragma unroll
    for (int k = 0; k < 32; k++) {
        float2 wl = swl2[k * 32 + lane];
        float2 wr = swr2[k * 32 + lane];
#pragma unroll
        for (int n = 0; n < 4; n++) {
            float m = rows[w][n][k];
            float h = rows[w][n][32 + k];
            a0[n] = fmaf(m, wl.x, fmaf(h, wr.x, a0[n]));
            a1[n] = fmaf(m, wl.y, fmaf(h, wr.y, a1[n]));
        }
    }
#pragma unroll
    for (int n = 0; n < 4; n++) {
        int node = nb + n;
        uint32_t j0 = (uint32_t)(node * 64 + lane);
        float v0 = drop_bit<DK1.a, DK1.b>(j0)       ? 0.f : 2.0f * a0[n];
        float v1 = drop_bit<DK1.a, DK1.b>(j0 + 32u) ? 0.f : 2.0f * a1[n];
        float ss = v0 * v0 + v1 * v1;
#pragma unroll
        for (int o = 16; o > 0; o >>= 1)
            ss += __shfl_xor_sync(0xffffffffu, ss, o);
        float scale = 1.0f / fmaxf(sqrtf(ss), 1e-12f);
        out[node * 64 + lane]      = v0 * scale;
        out[node * 64 + 32 + lane] = v1 * scale;
    }
}

// ---------------- launch -----------------------------------------------------
extern "C" void kernel_launch(void* const* d_in, const int* in_sizes, int n_in,
                              void* d_out, int out_size) {
    const float*    x   = (const float*)d_in[0];
    const uint32_t* ei  = (const uint32_t*)d_in[1];   // int32 or int64 (detected)
    const float*    W1l = (const float*)d_in[2];
    const float*    b1  = (const float*)d_in[3];
    const float*    W1r = (const float*)d_in[4];
    const float*    W2l = (const float*)d_in[5];
    const float*    b2  = (const float*)d_in[6];
    const float*    W2r = (const float*)d_in[7];
    float* out = (float*)d_out;

    k_pre<<<N_NODES / 32, 256>>>(x, W1l, W1r, ei);     // 3125 blocks
    k_prep<<<(N_EDGES + 255) / 256, 256>>>(ei);        // 6250 blocks
    k_scan_a<<<NSCAN_BLKS, SCAN_BLK>>>();
    k_scan_b<<<1, 256>>>();
    k_scan_c<<<NSCAN_BLKS, SCAN_BLK>>>();
    k_bucket<<<(N_EDGES + 255) / 256, 256>>>();        // 6250 blocks
    k_agg1<<<N_NODES / 8, 256>>>(b1);                  // 12500 blocks
    k_gather2<<<N_NODES / 8, 256>>>();                 // 12500 blocks
    k_gemm2<<<N_NODES / 32, 256>>>(W2l, b2, W2r, out); // 3125 blocks
}

// round 14
// speedup vs baseline: 1.1166x; 1.0155x over previous
#include <cuda_runtime.h>
#include <cuda_fp16.h>
#include <cstdint>

#define N_NODES 100000
#define N_EDGES 1600000
#define SCAN_BLK 512
#define NSCAN_BLKS 196   // 196*512 >= N_NODES

// ---------------- scratch (device globals; no allocation allowed) ----------
__device__ __half g_yh[N_NODES * 32];   // x @ W1_l  (fp16, gather source)
__device__ float  g_z[N_NODES * 32];    // x @ W1_r  (fp32)
__device__ __half g_h1h[N_NODES * 32];  // h1 fp16 (gather source, layer 2)
__device__ float  g_h1f[N_NODES * 32];  // h1 fp32 (dense self term)
__device__ float  g_m2[N_NODES * 32];   // layer-2 gathered mean
__device__ int2   g_edge[N_EDGES];      // packed (src, dst)
__device__ int    g_csr[N_EDGES];       // src ids grouped by dst
__device__ int    g_off[N_NODES + 1];   // counts -> exclusive offsets
__device__ int    g_part[N_NODES];      // scan partials
__device__ int    g_cur[N_NODES];       // bucket cursors
__device__ int    g_bsum[256];
__device__ int    g_is64;

// ---------------- JAX threefry2x32 (partitionable scheme) ------------------
struct TF2 { uint32_t a, b; };

__host__ __device__ constexpr uint32_t rotl32(uint32_t v, int r) {
    return (v << r) | (v >> (32 - r));
}

__host__ __device__ constexpr TF2 threefry(uint32_t k0, uint32_t k1,
                                           uint32_t x0, uint32_t x1) {
    const uint32_t ks0 = k0, ks1 = k1, ks2 = k0 ^ k1 ^ 0x1BD11BDAu;
    const int ra[4] = {13, 15, 26, 6};
    const int rb[4] = {17, 29, 16, 24};
    x0 += ks0; x1 += ks1;
#pragma unroll
    for (int i = 0; i < 4; i++) { x0 += x1; x1 = rotl32(x1, ra[i]); x1 ^= x0; }
    x0 += ks1; x1 += ks2 + 1u;
#pragma unroll
    for (int i = 0; i < 4; i++) { x0 += x1; x1 = rotl32(x1, rb[i]); x1 ^= x0; }
    x0 += ks2; x1 += ks0 + 2u;
#pragma unroll
    for (int i = 0; i < 4; i++) { x0 += x1; x1 = rotl32(x1, ra[i]); x1 ^= x0; }
    x0 += ks0; x1 += ks1 + 3u;
#pragma unroll
    for (int i = 0; i < 4; i++) { x0 += x1; x1 = rotl32(x1, rb[i]); x1 ^= x0; }
    x0 += ks1; x1 += ks2 + 4u;
#pragma unroll
    for (int i = 0; i < 4; i++) { x0 += x1; x1 = rotl32(x1, ra[i]); x1 ^= x0; }
    x0 += ks2; x1 += ks0 + 5u;
    return {x0, x1};
}

constexpr TF2 DK0 = threefry(0u, 42u, 0u, 0u);
constexpr TF2 DK1 = threefry(0u, 42u, 0u, 1u);

template <uint32_t K0, uint32_t K1>
__device__ __forceinline__ bool drop_bit(uint32_t j) {
    TF2 r = threefry(K0, K1, 0u, j);
    return ((r.a ^ r.b) >> 31) != 0;   // MSB set -> u >= 0.5 -> dropped
}

// ---------------- packed f32x2 helpers (sm_103a) ---------------------------
typedef unsigned long long ULL;
__device__ __forceinline__ ULL pk2(float x, float y) {
    ULL r;
    asm("mov.b64 %0, {%1, %2};" : "=l"(r) : "f"(x), "f"(y));
    return r;
}
__device__ __forceinline__ ULL fma2(ULL a, ULL b, ULL c) {
    ULL d;
    asm("fma.rn.f32x2 %0, %1, %2, %3;" : "=l"(d) : "l"(a), "l"(b), "l"(c));
    return d;
}
__device__ __forceinline__ void upk2(ULL v, float& x, float& y) {
    asm("mov.b64 {%0, %1}, %2;" : "=f"(x), "=f"(y) : "l"(v));
}

// ---------------- k_pre: dense pre-GEMM + resets + dtype detect -------------
__global__ void __launch_bounds__(256) k_pre(const float* __restrict__ x,
                      const float* __restrict__ Wl,
                      const float* __restrict__ Wr,
                      const uint32_t* __restrict__ ei) {
    __shared__ float2 swlr[64 * 32];      // (Wl, Wr) pairs, 16KB
    __shared__ float  rows[8][4][64];     // 8KB
    int tid = threadIdx.x;
    for (int i = tid; i < 2048; i += 256) swlr[i] = make_float2(Wl[i], Wr[i]);
    int gt = blockIdx.x * 256 + tid;
    if (gt <= N_NODES) g_off[gt] = 0;
    if (blockIdx.x == 0 && tid == 0) {
        int is64 = 1;
        for (int k = 0; k < 64; k++)
            if (ei[2 * k + 1] != 0u) { is64 = 0; break; }
        g_is64 = is64;
    }
    int w = tid >> 5, lane = tid & 31;
    int nb = blockIdx.x * 32 + w * 4;     // grid = 3125 exact
#pragma unroll
    for (int n = 0; n < 4; n++) {
        rows[w][n][lane]      = x[(nb + n) * 64 + lane];
        rows[w][n][32 + lane] = x[(nb + n) * 64 + 32 + lane];
    }
    __syncthreads();
    ULL acc[4];
#pragma unroll
    for (int n = 0; n < 4; n++) acc[n] = pk2(0.f, 0.f);
#pragma unroll
    for (int k = 0; k < 64; k++) {
        float2 wv = swlr[k * 32 + lane];
        ULL wp = pk2(wv.x, wv.y);
#pragma unroll
        for (int n = 0; n < 4; n++) {
            float xv = rows[w][n][k];
            acc[n] = fma2(pk2(xv, xv), wp, acc[n]);
        }
    }
#pragma unroll
    for (int n = 0; n < 4; n++) {
        float yl, yr;
        upk2(acc[n], yl, yr);
        g_yh[(nb + n) * 32 + lane] = __float2half_rn(yl);
        g_z[(nb + n) * 32 + lane]  = yr;
    }
}

// ---------------- CSR build ---------------------------------------------------
__global__ void k_prep(const uint32_t* __restrict__ ei) {
    int e = blockIdx.x * blockDim.x + threadIdx.x;
    if (e >= N_EDGES) return;
    int s, d;
    if (g_is64) {
        uint2 sv = reinterpret_cast<const uint2*>(ei)[e];
        uint2 dv = reinterpret_cast<const uint2*>(ei)[N_EDGES + e];
        s = (int)sv.x; d = (int)dv.x;
    } else {
        s = (int)ei[e];
        d = (int)ei[N_EDGES + e];
    }
    g_edge[e] = make_int2(s, d);
    atomicAdd(&g_off[d], 1);
}

__global__ void k_scan_a() {
    __shared__ int sh[SCAN_BLK];
    int i = blockIdx.x * SCAN_BLK + threadIdx.x;
    int v = (i < N_NODES) ? g_off[i] : 0;
    sh[threadIdx.x] = v;
    __syncthreads();
    for (int o = 1; o < SCAN_BLK; o <<= 1) {
        int t = (threadIdx.x >= o) ? sh[threadIdx.x - o] : 0;
        __syncthreads();
        sh[threadIdx.x] += t;
        __syncthreads();
    }
    if (i < N_NODES) g_part[i] = sh[threadIdx.x] - v;    // exclusive in-block
    if (threadIdx.x == SCAN_BLK - 1) g_bsum[blockIdx.x] = sh[threadIdx.x];
}

// apply: each block reduces preceding chunk totals itself, writes offsets.
__global__ void k_apply() {
    __shared__ int sh[SCAN_BLK];
    int tid = threadIdx.x, bid = blockIdx.x;
    int v = (tid < NSCAN_BLKS && tid < bid) ? g_bsum[tid] : 0;
    sh[tid] = v;
    __syncthreads();
    for (int o = SCAN_BLK / 2; o > 0; o >>= 1) {
        if (tid < o) sh[tid] += sh[tid + o];
        __syncthreads();
    }
    int base = sh[0];
    int i = bid * SCAN_BLK + tid;
    if (i < N_NODES) {
        int o = g_part[i] + base;
        g_off[i] = o;
        g_cur[i] = o;
    }
    if (bid == 0 && tid == 0) g_off[N_NODES] = N_EDGES;
}

__global__ void k_bucket() {
    int e = blockIdx.x * blockDim.x + threadIdx.x;
    if (e >= N_EDGES) return;
    int2 p = g_edge[e];
    int pos = atomicAdd(&g_cur[p.y], 1);
    g_csr[pos] = p.x;
}

// ---------------- fp16 gather: 16 lanes per row, 2 rows per iteration --------
// lane = r*16 + c (r in {0,1}, c = half2 column 0..15). Returns, in EVERY lane,
// the fp32 sums of columns (2*(lane&15), 2*(lane&15)+1) over all neighbors.
__device__ __forceinline__ float2 gather_h2(const __half2* __restrict__ buf,
                                            int beg, int end, int lane) {
    int r = lane >> 4;       // row-group 0/1
    int c = lane & 15;       // half2 column
    float acx = 0.f, acy = 0.f;
    int j = beg;
    for (; j + 4 <= end; j += 4) {
        int i0 = __ldg(g_csr + j + r);
        int i1 = __ldg(g_csr + j + 2 + r);
        float2 a = __half22float2(__ldg(buf + i0 * 16 + c));
        float2 b = __half22float2(__ldg(buf + i1 * 16 + c));
        acx += a.x + b.x;
        acy += a.y + b.y;
    }
    if (j + 2 <= end) {
        int i0 = __ldg(g_csr + j + r);
        float2 a = __half22float2(__ldg(buf + i0 * 16 + c));
        acx += a.x; acy += a.y;
        j += 2;
    }
    if (j < end && r == 0) {     // odd remainder handled by row-group 0 only
        int i0 = __ldg(g_csr + j);
        float2 a = __half22float2(__ldg(buf + i0 * 16 + c));
        acx += a.x; acy += a.y;
    }
    // combine the two row-groups
    acx += __shfl_xor_sync(0xffffffffu, acx, 16);
    acy += __shfl_xor_sync(0xffffffffu, acy, 16);
    return make_float2(acx, acy);
}

// layer 1: warp per node; fp16 gather-mean + bias + z + lrelu + dropout
__global__ void k_agg1(const float* __restrict__ b) {
    int w = threadIdx.x >> 5, lane = threadIdx.x & 31;
    int node = blockIdx.x * 8 + w;                    // grid = 12500 exact
    int beg = g_off[node], end = g_off[node + 1];
    float2 acc = gather_h2(reinterpret_cast<const __half2*>(g_yh), beg, end, lane);
    if (lane < 16) {
        int c2 = 2 * lane;
        float inv = 1.0f / fmaxf((float)(end - beg), 1.0f);
        float2 z2 = *reinterpret_cast<const float2*>(g_z + node * 32 + c2);
        float2 bb = *reinterpret_cast<const float2*>(b + c2);
        float v0 = fmaf(acc.x, inv, bb.x + z2.x);
        float v1 = fmaf(acc.y, inv, bb.y + z2.y);
        v0 = v0 > 0.f ? v0 : 0.01f * v0;
        v1 = v1 > 0.f ? v1 : 0.01f * v1;
        uint32_t jj = (uint32_t)(node * 32 + c2);
        v0 = drop_bit<DK0.a, DK0.b>(jj)      ? 0.f : 2.0f * v0;
        v1 = drop_bit<DK0.a, DK0.b>(jj + 1u) ? 0.f : 2.0f * v1;
        *reinterpret_cast<float2*>(g_h1f + node * 32 + c2) = make_float2(v0, v1);
        reinterpret_cast<__half2*>(g_h1h)[node * 16 + lane] =
            __floats2half2_rn(v0, v1);
    }
}

// layer 2 gather: warp per node; fp16 gather-mean of h1 -> g_m2 (fp32)
__global__ void k_gather2() {
    int w = threadIdx.x >> 5, lane = threadIdx.x & 31;
    int node = blockIdx.x * 8 + w;                    // grid = 12500 exact
    int beg = g_off[node], end = g_off[node + 1];
    float2 acc = gather_h2(reinterpret_cast<const __half2*>(g_h1h), beg, end, lane);
    if (lane < 16) {
        float inv = 1.0f / fmaxf((float)(end - beg), 1.0f);
        *reinterpret_cast<float2*>(g_m2 + node * 32 + 2 * lane) =
            make_float2(acc.x * inv, acc.y * inv);
    }
}

// layer 2 dense: GEMMs (4 nodes/warp, packed weights) + dropout + l2norm
__global__ void __launch_bounds__(256) k_gemm2(const float* __restrict__ Wl,
                       const float* __restrict__ b,
                       const float* __restrict__ Wr,
                       float* __restrict__ out) {
    __shared__ float2 swl2[32 * 32], swr2[32 * 32];   // 8KB + 8KB
    __shared__ float  rows[8][4][64];                 // 8KB
    int tid = threadIdx.x;
    for (int i = tid; i < 1024; i += 256) {
        int k = i >> 5, c = i & 31;
        swl2[i] = make_float2(Wl[k * 64 + c], Wl[k * 64 + 32 + c]);
        swr2[i] = make_float2(Wr[k * 64 + c], Wr[k * 64 + 32 + c]);
    }
    __syncthreads();
    int w = tid >> 5, lane = tid & 31;
    int nb = blockIdx.x * 32 + w * 4;                 // grid = 3125 exact
#pragma unroll
    for (int n = 0; n < 4; n++) {
        int node = nb + n;
        rows[w][n][lane]      = g_m2[node * 32 + lane];
        rows[w][n][32 + lane] = g_h1f[node * 32 + lane];
    }
    __syncwarp();
    float bb0 = b[lane], bb1 = b[32 + lane];
    float a0[4], a1[4];
#pragma unroll
    for (int n = 0; n < 4; n++) { a0[n] = bb0; a1[n] = bb1; }
#pragma unroll
    for (int k = 0; k < 32; k++) {
        float2 wl = swl2[k * 32 + lane];
        float2 wr = swr2[k * 32 + lane];
#pragma unroll
        for (int n = 0; n < 4; n++) {
            float m = rows[w][n][k];
            float h = rows[w][n][32 + k];
            a0[n] = fmaf(m, wl.x, fmaf(h, wr.x, a0[n]));
            a1[n] = fmaf(m, wl.y, fmaf(h, wr.y, a1[n]));
        }
    }
#pragma unroll
    for (int n = 0; n < 4; n++) {
        int node = nb + n;
        uint32_t j0 = (uint32_t)(node * 64 + lane);
        float v0 = drop_bit<DK1.a, DK1.b>(j0)       ? 0.f : 2.0f * a0[n];
        float v1 = drop_bit<DK1.a, DK1.b>(j0 + 32u) ? 0.f : 2.0f * a1[n];
        float ss = v0 * v0 + v1 * v1;
#pragma unroll
        for (int o = 16; o > 0; o >>= 1)
            ss += __shfl_xor_sync(0xffffffffu, ss, o);
        float scale = 1.0f / fmaxf(sqrtf(ss), 1e-12f);
        out[node * 64 + lane]      = v0 * scale;
        out[node * 64 + 32 + lane] = v1 * scale;
    }
}

// ---------------- launch -----------------------------------------------------
extern "C" void kernel_launch(void* const* d_in, const int* in_sizes, int n_in,
                              void* d_out, int out_size) {
    const float*    x   = (const float*)d_in[0];
    const uint32_t* ei  = (const uint32_t*)d_in[1];   // int32 or int64 (detected)
    const float*    W1l = (const float*)d_in[2];
    const float*    b1  = (const float*)d_in[3];
    const float*    W1r = (const float*)d_in[4];
    const float*    W2l = (const float*)d_in[5];
    const float*    b2  = (const float*)d_in[6];
    const float*    W2r = (const float*)d_in[7];
    float* out = (float*)d_out;

    k_pre<<<N_NODES / 32, 256>>>(x, W1l, W1r, ei);     // 3125 blocks
    k_prep<<<(N_EDGES + 255) / 256, 256>>>(ei);        // 6250 blocks
    k_scan_a<<<NSCAN_BLKS, SCAN_BLK>>>();
    k_apply<<<NSCAN_BLKS, SCAN_BLK>>>();
    k_bucket<<<(N_EDGES + 255) / 256, 256>>>();        // 6250 blocks
    k_agg1<<<N_NODES / 8, 256>>>(b1);                  // 12500 blocks
    k_gather2<<<N_NODES / 8, 256>>>();                 // 12500 blocks
    k_gemm2<<<N_NODES / 32, 256>>>(W2l, b2, W2r, out); // 3125 blocks
}